// round 16
// baseline (speedup 1.0000x reference)
#include <cuda_runtime.h>
#include <cuda_fp16.h>
#include <cstdint>

#define B_   1024
#define L_   256
#define C_   20
#define LC_  5120

#define TM   128
#define TN   128
#define NMT  8      // 1024/128
#define NNT  40     // 5120/128
#define NKT  80     // 64-wide k sub-tiles
#define TILE_BYTES 16384
#define KS   16     // K-chunks per work item
#define NWORK 120   // sum over nt of ceil(n(nt)/KS)

__device__ __align__(256) unsigned char g_x [NMT * NKT * TILE_BYTES];
__device__ __align__(256) unsigned char g_th[NNT * NKT * TILE_BYTES];

__device__ __forceinline__ uint32_t smem_u32(const void* p) {
    uint32_t a;
    asm("{ .reg .u64 t; cvta.to.shared.u64 t, %1; cvt.u32.u64 %0, t; }" : "=r"(a) : "l"(p));
    return a;
}
__device__ __forceinline__ void cp16(uint32_t d, const unsigned char* s) {
    asm volatile("cp.async.cg.shared.global [%0], [%1], 16;" :: "r"(d), "l"(s) : "memory");
}
__device__ __forceinline__ void prefetchL2(const void* p) {
    asm volatile("prefetch.global.L2 [%0];" :: "l"(p));
}
#define MBAR_INIT(a, n) asm volatile("mbarrier.init.shared.b64 [%0], %1;" :: "r"(a), "r"(n) : "memory")
#define MBAR_ARRIVE(a)  asm volatile("mbarrier.arrive.release.cta.shared.b64 _, [%0];" :: "r"(a) : "memory")
#define CP_MBAR_ARRIVE(a) asm volatile("cp.async.mbarrier.arrive.noinc.shared.b64 [%0];" :: "r"(a) : "memory")
#define MBAR_WAIT(addr, ph) do {                                                        \
    uint32_t _m = (addr), _p = (ph), _d;                                                \
    asm volatile("{\n .reg .pred p;\n"                                                  \
        " mbarrier.try_wait.parity.acquire.cta.shared::cta.b64 p, [%1], %2;\n"          \
        " selp.b32 %0, 1, 0, p;\n}" : "=r"(_d) : "r"(_m), "r"(_p) : "memory");          \
    if (!_d) {                                                                          \
        asm volatile("{\n .reg .pred P1;\n"                                             \
            "W%=:\n mbarrier.try_wait.parity.acquire.cta.shared::cta.b64 P1, [%0], %1, 0x989680;\n" \
            " @P1 bra.uni D%=;\n bra.uni W%=;\nD%=:\n}" :: "r"(_m), "r"(_p) : "memory"); \
    } } while (0)
#define MBAR_WAIT_RELAXED(addr, ph) do {                                                \
    uint32_t _m = (addr), _p = (ph), _d;                                                \
    asm volatile("{\n .reg .pred p;\n"                                                  \
        " mbarrier.try_wait.parity.relaxed.cta.shared::cta.b64 p, [%1], %2;\n"          \
        " selp.b32 %0, 1, 0, p;\n}" : "=r"(_d) : "r"(_m), "r"(_p) : "memory");          \
    if (!_d) {                                                                          \
        asm volatile("{\n .reg .pred P1;\n"                                             \
            "W%=:\n mbarrier.try_wait.parity.relaxed.cta.shared::cta.b64 P1, [%0], %1, 0x989680;\n" \
            " @P1 bra.uni D%=;\n bra.uni W%=;\nD%=:\n}" :: "r"(_m), "r"(_p) : "memory"); \
    } } while (0)

__device__ __forceinline__ void ldsm4(uint32_t* r, uint32_t addr) {
    asm volatile("ldmatrix.sync.aligned.m8n8.x4.shared.b16 {%0,%1,%2,%3}, [%4];"
        : "=r"(r[0]), "=r"(r[1]), "=r"(r[2]), "=r"(r[3]) : "r"(addr));
}
__device__ __forceinline__ void mma16816(float* d, const uint32_t* a, const uint32_t* b) {
    asm volatile("mma.sync.aligned.m16n8k16.row.col.f32.f16.f16.f32 "
        "{%0,%1,%2,%3}, {%4,%5,%6,%7}, {%8,%9}, {%0,%1,%2,%3};"
        : "+f"(d[0]), "+f"(d[1]), "+f"(d[2]), "+f"(d[3])
        : "r"(a[0]), "r"(a[1]), "r"(a[2]), "r"(a[3]), "r"(b[0]), "r"(b[1]));
}

// --- merged prep: blockIdx.x<40 -> theta tile; else -> x tile + lin partial (+theta0 @kt=0) ---
__global__ __launch_bounds__(256)
void prep_kernel(const float* __restrict__ x, const float* __restrict__ theta_lc,
                 const float* __restrict__ th, const float* __restrict__ theta0,
                 float* __restrict__ out) {
    __shared__ float ts[64][132];
    const int kt = blockIdx.y;
    if (blockIdx.x < NNT) {
        const int nt = blockIdx.x;
        const int j0 = nt * TN, k0 = kt * 64;
        const int Kend = ((j0 + TN - 1) / C_) * C_;
        if (k0 >= Kend) return;                  // fully masked: never read by gemm
        #pragma unroll
        for (int it = 0; it < 8; it++) {
            const int e = it * 256 + threadIdx.x;
            const int rk = e >> 5, j4 = (e & 31) << 2;
            const float4 v = *(const float4*)(th + (size_t)(k0 + rk) * LC_ + j0 + j4);
            *(float4*)&ts[rk][j4] = v;
        }
        __syncthreads();
        unsigned char* dst = g_th + (size_t)(nt * NKT + kt) * TILE_BYTES;
        for (int q = threadIdx.x; q < 1024; q += 256) {
            const int r = q >> 3, c0 = (q & 7) << 3;
            const int l2 = (j0 + r) / C_;
            union { __half h[8]; uint4 u; } pk;
            #pragma unroll
            for (int i = 0; i < 8; i++) {
                const int l1 = (k0 + c0 + i) / C_;
                pk.h[i] = __float2half_rn((l1 < l2) ? ts[c0 + i][r] : 0.0f);
            }
            uint32_t off = (uint32_t)(r * 128 + c0 * 2);
            off ^= (off >> 3) & 0x70u;
            *(uint4*)(dst + off) = pk.u;
        }
    } else {
        const int mt = blockIdx.x - NNT;
        const float* src = x + (size_t)(mt * TM) * LC_ + kt * 64;
        const float* tl  = theta_lc + kt * 64;
        unsigned char* dst = g_x + (size_t)(mt * NKT + kt) * TILE_BYTES;
        for (int q = threadIdx.x; q < 1024; q += 256) {
            const int r = q >> 3, c0 = (q & 7) << 3;
            const float4 v0 = *(const float4*)(src + (size_t)r * LC_ + c0);
            const float4 v1 = *(const float4*)(src + (size_t)r * LC_ + c0 + 4);
            union { __half2 h2[4]; uint4 u; } pk;
            pk.h2[0] = __floats2half2_rn(v0.x, v0.y);
            pk.h2[1] = __floats2half2_rn(v0.z, v0.w);
            pk.h2[2] = __floats2half2_rn(v1.x, v1.y);
            pk.h2[3] = __floats2half2_rn(v1.z, v1.w);
            uint32_t off = (uint32_t)(r * 128 + c0 * 2);
            off ^= (off >> 3) & 0x70u;
            *(uint4*)(dst + off) = pk.u;
            const float4 t0 = *(const float4*)(tl + c0);
            const float4 t1 = *(const float4*)(tl + c0 + 4);
            float s = v0.x * t0.x + v0.y * t0.y + v0.z * t0.z + v0.w * t0.w
                    + v1.x * t1.x + v1.y * t1.y + v1.z * t1.z + v1.w * t1.w;
            s += __shfl_xor_sync(0xffffffffu, s, 1);
            s += __shfl_xor_sync(0xffffffffu, s, 2);
            s += __shfl_xor_sync(0xffffffffu, s, 4);
            if ((q & 7) == 0) {
                if (kt == 0) s += theta0[0];
                atomicAdd(out + mt * TM + r, s);
            }
        }
    }
}

// --- HMMA fused GEMM + diagonal dot, mbarrier-pipelined, early empty-arrive ---
__global__ __launch_bounds__(128, 3)
void gemm_kernel(const float* __restrict__ x, float* __restrict__ out) {
    extern __shared__ unsigned char dynsm[];
    __shared__ float obuf[128];
    __shared__ __align__(8) unsigned long long mb_full[2], mb_empty[2];

    const int tid = threadIdx.x;
    const int w = tid >> 5, l = tid & 31;
    const int wm = w >> 1, wn = w & 1;
    const int mt = blockIdx.x;

    int nt = 0, z = 0;
    {
        int y = blockIdx.y, acc = 0;
        #pragma unroll 1
        for (int q = NNT - 1; q >= 0; q--) {
            const int cnt = (q + 8) >> 3;           // ceil((2q+2)/16)
            if (y < acc + cnt) { nt = q; z = y - acc; break; }
            acc += cnt;
        }
    }
    const int j0 = nt * TN;
    const int Kend = ((j0 + TN - 1) / C_) * C_;
    const int n = (Kend + 63) / 64;
    const int c0 = z * KS;
    const int len = min(n, c0 + KS) - c0;

    {
        const float* xrow = x + (size_t)(mt * TM + tid) * LC_ + j0;
        prefetchL2(xrow);
        prefetchL2(xrow + 32);
        prefetchL2(xrow + 64);
        prefetchL2(xrow + 96);
    }

    const uint32_t smem = (smem_u32(dynsm) + 1023u) & ~1023u;
    const uint32_t fb = smem_u32(&mb_full[0]);
    const uint32_t eb = smem_u32(&mb_empty[0]);
    if (tid == 0) {
        MBAR_INIT(fb, 128);      MBAR_INIT(fb + 8u, 128);
        MBAR_INIT(eb, 4);        MBAR_INIT(eb + 8u, 4);
    }
    __syncthreads();

    const unsigned char* aSrc = g_x  + (size_t)(mt * NKT + c0) * TILE_BYTES;
    const unsigned char* bSrc = g_th + (size_t)(nt * NKT + c0) * TILE_BYTES;

    float acc[4][8][4] = {};

    const int rowA = wm * 64 + (l & 15);
    const int rowB = wn * 64 + (l & 7) + ((l >> 4) << 3);
    const int aK = l >> 4;
    const int bK = (l >> 3) & 1;
    const int xs = l & 7;

    #pragma unroll
    for (int pc = 0; pc < 2; pc++) {
        if (pc < len) {
            const uint32_t dst = smem + (uint32_t)pc * 32768u;
            const unsigned char* a = aSrc + (size_t)pc * TILE_BYTES;
            const unsigned char* b = bSrc + (size_t)pc * TILE_BYTES;
            #pragma unroll
            for (int i = 0; i < 8; i++) {
                cp16(dst + (uint32_t)(i * 2048 + tid * 16), a + i * 2048 + tid * 16);
                cp16(dst + 16384u + (uint32_t)(i * 2048 + tid * 16), b + i * 2048 + tid * 16);
            }
            CP_MBAR_ARRIVE(fb + 8u * pc);
        }
    }

    for (int t = 0; t < len; t++) {
        const int k = t >> 1, s = t & 1;
        MBAR_WAIT(fb + 8u * s, k & 1);

        const uint32_t tA = smem + (uint32_t)s * 32768u;
        const uint32_t tB = tA + 16384u;
        #pragma unroll
        for (int ks = 0; ks < 4; ks++) {
            uint32_t afr[4][4], bfr[4][4];
            #pragma unroll
            for (int mi = 0; mi < 4; mi++)
                ldsm4(afr[mi], tA + (uint32_t)((rowA + mi * 16) * 128)
                               + (uint32_t)(((ks * 2 + aK) ^ xs) << 4));
            #pragma unroll
            for (int np = 0; np < 4; np++)
                ldsm4(bfr[np], tB + (uint32_t)((rowB + np * 16) * 128)
                               + (uint32_t)(((ks * 2 + bK) ^ xs) << 4));
            if (ks == 3 && l == 0) MBAR_ARRIVE(eb + 8u * s);
            #pragma unroll
            for (int mi = 0; mi < 4; mi++) {
                #pragma unroll
                for (int np = 0; np < 4; np++) {
                    mma16816(acc[mi][np * 2 + 0], afr[mi], &bfr[np][0]);
                    mma16816(acc[mi][np * 2 + 1], afr[mi], &bfr[np][2]);
                }
            }
        }

        if (t + 2 < len) {
            MBAR_WAIT_RELAXED(eb + 8u * s, k & 1);
            const unsigned char* a = aSrc + (size_t)(t + 2) * TILE_BYTES;
            const unsigned char* b = bSrc + (size_t)(t + 2) * TILE_BYTES;
            #pragma unroll
            for (int i = 0; i < 8; i++) {
                cp16(tA + (uint32_t)(i * 2048 + tid * 16), a + i * 2048 + tid * 16);
                cp16(tB + (uint32_t)(i * 2048 + tid * 16), b + i * 2048 + tid * 16);
            }
            CP_MBAR_ARRIVE(fb + 8u * s);
        }
    }

    __syncthreads();
    obuf[tid] = 0.0f;
    __syncthreads();
    const int q = l >> 2, ql = l & 3;
    #pragma unroll
    for (int mi = 0; mi < 4; mi++) {
        #pragma unroll
        for (int h = 0; h < 2; h++) {
            const int bl = wm * 64 + mi * 16 + q + h * 8;
            const float* xr = x + (size_t)(mt * TM + bl) * LC_ + j0 + wn * 64 + ql * 2;
            float p = 0.0f;
            #pragma unroll
            for (int nf = 0; nf < 8; nf++) {
                const float2 xv = *(const float2*)(xr + nf * 8);
                p += acc[mi][nf][h * 2 + 0] * xv.x + acc[mi][nf][h * 2 + 1] * xv.y;
            }
            p += __shfl_xor_sync(0xffffffffu, p, 1);
            p += __shfl_xor_sync(0xffffffffu, p, 2);
            if (ql == 0) atomicAdd(obuf + bl, p);
        }
    }
    __syncthreads();
    atomicAdd(out + mt * TM + tid, obuf[tid]);
}

extern "C" void kernel_launch(void* const* d_in, const int* in_sizes, int n_in,
                              void* d_out, int out_size) {
    const float* x_lc       = (const float*)d_in[0];
    const float* theta_0    = (const float*)d_in[1];
    const float* theta_lc   = (const float*)d_in[2];
    const float* theta_lclc = (const float*)d_in[3];
    float* out = (float*)d_out;

    cudaFuncSetAttribute(gemm_kernel,
                         cudaFuncAttributeMaxDynamicSharedMemorySize, 66560);

    cudaMemsetAsync(out, 0, B_ * sizeof(float), 0);
    prep_kernel<<<dim3(NNT + NMT, NKT), 256>>>(x_lc, theta_lc, theta_lclc, theta_0, out);
    gemm_kernel<<<dim3(NMT, NWORK), 128, 66560>>>(x_lc, out);
}

// round 17
// speedup vs baseline: 1.0374x; 1.0374x over previous
#include <cuda_runtime.h>
#include <cuda_fp16.h>
#include <cstdint>

#define B_   1024
#define L_   256
#define C_   20
#define LC_  5120

#define TM   128
#define TN   128
#define NMT  8      // 1024/128
#define NNT  40     // 5120/128
#define NKT  80     // 64-wide k sub-tiles
#define TILE_BYTES 16384
#define KS   16     // K-chunks per work item
#define NWORK 120   // sum over nt of ceil(n(nt)/KS)

__device__ __align__(256) unsigned char g_x [NMT * NKT * TILE_BYTES];
__device__ __align__(256) unsigned char g_th[NNT * NKT * TILE_BYTES];

__device__ __forceinline__ uint32_t smem_u32(const void* p) {
    uint32_t a;
    asm("{ .reg .u64 t; cvta.to.shared.u64 t, %1; cvt.u32.u64 %0, t; }" : "=r"(a) : "l"(p));
    return a;
}
__device__ __forceinline__ void cp16(uint32_t d, const unsigned char* s) {
    asm volatile("cp.async.cg.shared.global [%0], [%1], 16;" :: "r"(d), "l"(s) : "memory");
}
__device__ __forceinline__ void prefetchL2(const void* p) {
    asm volatile("prefetch.global.L2 [%0];" :: "l"(p));
}
#define MBAR_INIT(a, n) asm volatile("mbarrier.init.shared.b64 [%0], %1;" :: "r"(a), "r"(n) : "memory")
#define MBAR_ARRIVE(a)  asm volatile("mbarrier.arrive.release.cta.shared.b64 _, [%0];" :: "r"(a) : "memory")
#define CP_MBAR_ARRIVE(a) asm volatile("cp.async.mbarrier.arrive.noinc.shared.b64 [%0];" :: "r"(a) : "memory")
#define MBAR_WAIT(addr, ph) do {                                                        \
    uint32_t _m = (addr), _p = (ph), _d;                                                \
    asm volatile("{\n .reg .pred p;\n"                                                  \
        " mbarrier.try_wait.parity.acquire.cta.shared::cta.b64 p, [%1], %2;\n"          \
        " selp.b32 %0, 1, 0, p;\n}" : "=r"(_d) : "r"(_m), "r"(_p) : "memory");          \
    if (!_d) {                                                                          \
        asm volatile("{\n .reg .pred P1;\n"                                             \
            "W%=:\n mbarrier.try_wait.parity.acquire.cta.shared::cta.b64 P1, [%0], %1, 0x989680;\n" \
            " @P1 bra.uni D%=;\n bra.uni W%=;\nD%=:\n}" :: "r"(_m), "r"(_p) : "memory"); \
    } } while (0)
#define MBAR_WAIT_RELAXED(addr, ph) do {                                                \
    uint32_t _m = (addr), _p = (ph), _d;                                                \
    asm volatile("{\n .reg .pred p;\n"                                                  \
        " mbarrier.try_wait.parity.relaxed.cta.shared::cta.b64 p, [%1], %2;\n"          \
        " selp.b32 %0, 1, 0, p;\n}" : "=r"(_d) : "r"(_m), "r"(_p) : "memory");          \
    if (!_d) {                                                                          \
        asm volatile("{\n .reg .pred P1;\n"                                             \
            "W%=:\n mbarrier.try_wait.parity.relaxed.cta.shared::cta.b64 P1, [%0], %1, 0x989680;\n" \
            " @P1 bra.uni D%=;\n bra.uni W%=;\nD%=:\n}" :: "r"(_m), "r"(_p) : "memory"); \
    } } while (0)

__device__ __forceinline__ void ldsm4(uint32_t* r, uint32_t addr) {
    asm volatile("ldmatrix.sync.aligned.m8n8.x4.shared.b16 {%0,%1,%2,%3}, [%4];"
        : "=r"(r[0]), "=r"(r[1]), "=r"(r[2]), "=r"(r[3]) : "r"(addr));
}
__device__ __forceinline__ void mma16816(float* d, const uint32_t* a, const uint32_t* b) {
    asm volatile("mma.sync.aligned.m16n8k16.row.col.f32.f16.f16.f32 "
        "{%0,%1,%2,%3}, {%4,%5,%6,%7}, {%8,%9}, {%0,%1,%2,%3};"
        : "+f"(d[0]), "+f"(d[1]), "+f"(d[2]), "+f"(d[3])
        : "r"(a[0]), "r"(a[1]), "r"(a[2]), "r"(a[3]), "r"(b[0]), "r"(b[1]));
}

// --- merged prep (scalar staging — fastest measured): theta tiles | x tiles + lin ---
__global__ __launch_bounds__(256)
void prep_kernel(const float* __restrict__ x, const float* __restrict__ theta_lc,
                 const float* __restrict__ th, const float* __restrict__ theta0,
                 float* __restrict__ out) {
    __shared__ float ts[64][129];
    const int kt = blockIdx.y;
    if (blockIdx.x < NNT) {
        const int nt = blockIdx.x;
        const int j0 = nt * TN, k0 = kt * 64;
        const int Kend = ((j0 + TN - 1) / C_) * C_;
        if (k0 >= Kend) return;                  // fully masked: never read by gemm
        for (int e = threadIdx.x; e < 64 * 128; e += 256) {
            const int rk = e >> 7, jj = e & 127;
            ts[rk][jj] = th[(size_t)(k0 + rk) * LC_ + j0 + jj];
        }
        __syncthreads();
        unsigned char* dst = g_th + (size_t)(nt * NKT + kt) * TILE_BYTES;
        for (int q = threadIdx.x; q < 1024; q += 256) {
            const int r = q >> 3, c0 = (q & 7) << 3;
            const int l2 = (j0 + r) / C_;
            union { __half h[8]; uint4 u; } pk;
            #pragma unroll
            for (int i = 0; i < 8; i++) {
                const int l1 = (k0 + c0 + i) / C_;
                pk.h[i] = __float2half_rn((l1 < l2) ? ts[c0 + i][r] : 0.0f);
            }
            uint32_t off = (uint32_t)(r * 128 + c0 * 2);
            off ^= (off >> 3) & 0x70u;
            *(uint4*)(dst + off) = pk.u;
        }
    } else {
        const int mt = blockIdx.x - NNT;
        const float* src = x + (size_t)(mt * TM) * LC_ + kt * 64;
        const float* tl  = theta_lc + kt * 64;
        unsigned char* dst = g_x + (size_t)(mt * NKT + kt) * TILE_BYTES;
        for (int q = threadIdx.x; q < 1024; q += 256) {
            const int r = q >> 3, c0 = (q & 7) << 3;
            const float4 v0 = *(const float4*)(src + (size_t)r * LC_ + c0);
            const float4 v1 = *(const float4*)(src + (size_t)r * LC_ + c0 + 4);
            union { __half2 h2[4]; uint4 u; } pk;
            pk.h2[0] = __floats2half2_rn(v0.x, v0.y);
            pk.h2[1] = __floats2half2_rn(v0.z, v0.w);
            pk.h2[2] = __floats2half2_rn(v1.x, v1.y);
            pk.h2[3] = __floats2half2_rn(v1.z, v1.w);
            uint32_t off = (uint32_t)(r * 128 + c0 * 2);
            off ^= (off >> 3) & 0x70u;
            *(uint4*)(dst + off) = pk.u;
            const float4 t0 = *(const float4*)(tl + c0);
            const float4 t1 = *(const float4*)(tl + c0 + 4);
            float s = v0.x * t0.x + v0.y * t0.y + v0.z * t0.z + v0.w * t0.w
                    + v1.x * t1.x + v1.y * t1.y + v1.z * t1.z + v1.w * t1.w;
            s += __shfl_xor_sync(0xffffffffu, s, 1);
            s += __shfl_xor_sync(0xffffffffu, s, 2);
            s += __shfl_xor_sync(0xffffffffu, s, 4);
            if ((q & 7) == 0) {
                if (kt == 0) s += theta0[0];
                atomicAdd(out + mt * TM + r, s);
            }
        }
    }
}

// --- HMMA fused GEMM + diagonal dot, mbarrier-pipelined, early empty-arrive ---
__global__ __launch_bounds__(128, 3)
void gemm_kernel(const float* __restrict__ x, float* __restrict__ out) {
    extern __shared__ unsigned char dynsm[];
    __shared__ float obuf[128];
    __shared__ __align__(8) unsigned long long mb_full[2], mb_empty[2];

    const int tid = threadIdx.x;
    const int w = tid >> 5, l = tid & 31;
    const int wm = w >> 1, wn = w & 1;
    const int mt = blockIdx.x;

    int nt = 0, z = 0;
    {
        int y = blockIdx.y, acc = 0;
        #pragma unroll 1
        for (int q = NNT - 1; q >= 0; q--) {
            const int cnt = (q + 8) >> 3;           // ceil((2q+2)/16)
            if (y < acc + cnt) { nt = q; z = y - acc; break; }
            acc += cnt;
        }
    }
    const int j0 = nt * TN;
    const int Kend = ((j0 + TN - 1) / C_) * C_;
    const int n = (Kend + 63) / 64;
    const int c0 = z * KS;
    const int len = min(n, c0 + KS) - c0;

    {
        const float* xrow = x + (size_t)(mt * TM + tid) * LC_ + j0;
        prefetchL2(xrow);
        prefetchL2(xrow + 32);
        prefetchL2(xrow + 64);
        prefetchL2(xrow + 96);
    }

    const uint32_t smem = (smem_u32(dynsm) + 1023u) & ~1023u;
    const uint32_t fb = smem_u32(&mb_full[0]);
    const uint32_t eb = smem_u32(&mb_empty[0]);
    if (tid == 0) {
        MBAR_INIT(fb, 128);      MBAR_INIT(fb + 8u, 128);
        MBAR_INIT(eb, 4);        MBAR_INIT(eb + 8u, 4);
    }
    __syncthreads();

    const unsigned char* aSrc = g_x  + (size_t)(mt * NKT + c0) * TILE_BYTES;
    const unsigned char* bSrc = g_th + (size_t)(nt * NKT + c0) * TILE_BYTES;

    float acc[4][8][4] = {};

    const int rowA = wm * 64 + (l & 15);
    const int rowB = wn * 64 + (l & 7) + ((l >> 4) << 3);
    const int aK = l >> 4;
    const int bK = (l >> 3) & 1;
    const int xs = l & 7;

    #pragma unroll
    for (int pc = 0; pc < 2; pc++) {
        if (pc < len) {
            const uint32_t dst = smem + (uint32_t)pc * 32768u;
            const unsigned char* a = aSrc + (size_t)pc * TILE_BYTES;
            const unsigned char* b = bSrc + (size_t)pc * TILE_BYTES;
            #pragma unroll
            for (int i = 0; i < 8; i++) {
                cp16(dst + (uint32_t)(i * 2048 + tid * 16), a + i * 2048 + tid * 16);
                cp16(dst + 16384u + (uint32_t)(i * 2048 + tid * 16), b + i * 2048 + tid * 16);
            }
            CP_MBAR_ARRIVE(fb + 8u * pc);
        }
    }

    for (int t = 0; t < len; t++) {
        const int k = t >> 1, s = t & 1;
        MBAR_WAIT(fb + 8u * s, k & 1);

        const uint32_t tA = smem + (uint32_t)s * 32768u;
        const uint32_t tB = tA + 16384u;
        #pragma unroll
        for (int ks = 0; ks < 4; ks++) {
            uint32_t afr[4][4], bfr[4][4];
            #pragma unroll
            for (int mi = 0; mi < 4; mi++)
                ldsm4(afr[mi], tA + (uint32_t)((rowA + mi * 16) * 128)
                               + (uint32_t)(((ks * 2 + aK) ^ xs) << 4));
            #pragma unroll
            for (int np = 0; np < 4; np++)
                ldsm4(bfr[np], tB + (uint32_t)((rowB + np * 16) * 128)
                               + (uint32_t)(((ks * 2 + bK) ^ xs) << 4));
            if (ks == 3 && l == 0) MBAR_ARRIVE(eb + 8u * s);
            #pragma unroll
            for (int mi = 0; mi < 4; mi++) {
                #pragma unroll
                for (int np = 0; np < 4; np++) {
                    mma16816(acc[mi][np * 2 + 0], afr[mi], &bfr[np][0]);
                    mma16816(acc[mi][np * 2 + 1], afr[mi], &bfr[np][2]);
                }
            }
        }

        if (t + 2 < len) {
            MBAR_WAIT_RELAXED(eb + 8u * s, k & 1);
            const unsigned char* a = aSrc + (size_t)(t + 2) * TILE_BYTES;
            const unsigned char* b = bSrc + (size_t)(t + 2) * TILE_BYTES;
            #pragma unroll
            for (int i = 0; i < 8; i++) {
                cp16(tA + (uint32_t)(i * 2048 + tid * 16), a + i * 2048 + tid * 16);
                cp16(tB + (uint32_t)(i * 2048 + tid * 16), b + i * 2048 + tid * 16);
            }
            CP_MBAR_ARRIVE(fb + 8u * s);
        }
    }

    __syncthreads();
    obuf[tid] = 0.0f;
    __syncthreads();
    const int q = l >> 2, ql = l & 3;
    #pragma unroll
    for (int mi = 0; mi < 4; mi++) {
        #pragma unroll
        for (int h = 0; h < 2; h++) {
            const int bl = wm * 64 + mi * 16 + q + h * 8;
            const float* xr = x + (size_t)(mt * TM + bl) * LC_ + j0 + wn * 64 + ql * 2;
            float p = 0.0f;
            #pragma unroll
            for (int nf = 0; nf < 8; nf++) {
                const float2 xv = *(const float2*)(xr + nf * 8);
                p += acc[mi][nf][h * 2 + 0] * xv.x + acc[mi][nf][h * 2 + 1] * xv.y;
            }
            p += __shfl_xor_sync(0xffffffffu, p, 1);
            p += __shfl_xor_sync(0xffffffffu, p, 2);
            if (ql == 0) atomicAdd(obuf + bl, p);
        }
    }
    __syncthreads();
    atomicAdd(out + mt * TM + tid, obuf[tid]);
}

extern "C" void kernel_launch(void* const* d_in, const int* in_sizes, int n_in,
                              void* d_out, int out_size) {
    const float* x_lc       = (const float*)d_in[0];
    const float* theta_0    = (const float*)d_in[1];
    const float* theta_lc   = (const float*)d_in[2];
    const float* theta_lclc = (const float*)d_in[3];
    float* out = (float*)d_out;

    cudaFuncSetAttribute(gemm_kernel,
                         cudaFuncAttributeMaxDynamicSharedMemorySize, 66560);

    cudaMemsetAsync(out, 0, B_ * sizeof(float), 0);
    prep_kernel<<<dim3(NNT + NMT, NKT), 256>>>(x_lc, theta_lc, theta_lclc, theta_0, out);
    gemm_kernel<<<dim3(NMT, NWORK), 128, 66560>>>(x_lc, out);
}